// round 2
// baseline (speedup 1.0000x reference)
#include <cuda_runtime.h>

// ---------------------------------------------------------------------------
// Problem constants
// ---------------------------------------------------------------------------
#define NB    64          // batch
#define ZD    128         // latent dim
#define CIN   8
#define LL    1024        // W*H
#define C0C   256         // attention channels
#define CQKC  32
#define FFC   64          // filters
#define GG    65536       // NB * LL (total positions)

// ---------------------------------------------------------------------------
// Device scratch (allocation-free rule: __device__ globals)
// ---------------------------------------------------------------------------
__device__ __align__(16) float g_x0 [NB * CIN * LL];          //  2 MB  [b][c][l]
__device__ __align__(16) float g_y0 [(size_t)GG * C0C];       // 64 MB  [g][256] conv0 raw
__device__ __align__(16) float g_xa [(size_t)GG * C0C];       // 64 MB  [g][256] bn+relu
__device__ __align__(16) float g_qkv[(size_t)GG * 320];       // 80 MB  [g][q32|k32|v256]
__device__ __align__(16) float g_E  [(size_t)NB * LL * LL];   // 256 MB [b][i][j]
__device__ __align__(16) float g_att[(size_t)GG * C0C];       // 64 MB  [g][256]
__device__ __align__(16) float g_x1 [(size_t)GG * FFC];       // 16 MB  [g][64]
__device__ float g_pS[C0C * 64];
__device__ float g_pQ[C0C * 64];
__device__ __align__(16) float g_scale0[C0C], g_shift0[C0C];
__device__ __align__(16) float g_scale1[FFC], g_shift1[FFC];

// ---------------------------------------------------------------------------
// Generic tiled SGEMM: C[m,n] = sum_k A[m,k] * B(k,n)  (+bias[n]) (+fused resid)
//   BNT=1 : B stored [N,K] row-major  (dot-of-rows)   -> B[n*ldb + k]
//   BNT=0 : B stored [K,N] row-major                   -> B[k*ldb + n]
//   FUSE=1: C = gamma * acc + resid   (resid layout == C layout, stride sC)
// 128x128x8 tile, 256 threads, 8x8 microtile, register-prefetch pipelined.
// Requires K % 8 == 0, N % 4 == 0, lda/ldb/ldc % 4 == 0, 16B-aligned bases.
// ---------------------------------------------------------------------------
template<int BNT, int FUSE>
__global__ __launch_bounds__(256)
void sgemm_kernel(const float* __restrict__ A, const float* __restrict__ Bm,
                  const float* __restrict__ bias, const float* __restrict__ resid,
                  const float* __restrict__ gammaPtr, float* __restrict__ C,
                  int M, int N, int K, int lda, int ldb, int ldc,
                  long long sA, long long sB, long long sC)
{
    __shared__ float As[8][128];
    __shared__ float Bs[8][128];

    const int bz = blockIdx.z;
    A  += (long long)bz * sA;
    Bm += (long long)bz * sB;
    C  += (long long)bz * sC;
    const float* Rs = resid;
    if (FUSE) Rs = resid + (long long)bz * sC;

    const int tid = threadIdx.x;
    const int m0 = blockIdx.y * 128;
    const int n0 = blockIdx.x * 128;

    const int aRow = tid >> 1;          // 0..127
    const int aK   = (tid & 1) << 2;    // 0 or 4
    const int bnK  = tid >> 5;          // 0..7   (NN path)
    const int bnN  = (tid & 31) << 2;   // 0..124 (NN path)

    const int tr = (tid >> 4) << 3;     // 0..120
    const int tc = (tid & 15) << 3;     // 0..120

    const bool aOK = (m0 + aRow) < M;                 // per-thread, loop-invariant
    const bool bOK = BNT ? ((n0 + aRow) < N) : ((n0 + bnN) < N);
    const float* aPtr = A + (long long)(m0 + aRow) * lda + aK;
    const float* bPtr = BNT ? (Bm + (long long)(n0 + aRow) * ldb + aK)
                            : (Bm + (long long)bnK * ldb + (n0 + bnN));

    float acc[8][8];
#pragma unroll
    for (int i = 0; i < 8; i++)
#pragma unroll
        for (int j = 0; j < 8; j++) acc[i][j] = 0.f;

    // ---- prefetch tile 0 into registers ----
    float4 aReg = make_float4(0.f, 0.f, 0.f, 0.f);
    float4 bReg = make_float4(0.f, 0.f, 0.f, 0.f);
    if (aOK) aReg = *(const float4*)aPtr;
    if (bOK) bReg = *(const float4*)bPtr;

    for (int k0 = 0; k0 < K; k0 += 8) {
        // ---- commit prefetched registers to smem ----
        As[aK + 0][aRow] = aReg.x; As[aK + 1][aRow] = aReg.y;
        As[aK + 2][aRow] = aReg.z; As[aK + 3][aRow] = aReg.w;
        if (BNT) {
            Bs[aK + 0][aRow] = bReg.x; Bs[aK + 1][aRow] = bReg.y;
            Bs[aK + 2][aRow] = bReg.z; Bs[aK + 3][aRow] = bReg.w;
        } else {
            *(float4*)&Bs[bnK][bnN] = bReg;
        }
        __syncthreads();

        // ---- prefetch next tile while computing this one ----
        if (k0 + 8 < K) {
            aReg = make_float4(0.f, 0.f, 0.f, 0.f);
            bReg = make_float4(0.f, 0.f, 0.f, 0.f);
            if (aOK) aReg = *(const float4*)(aPtr + (k0 + 8));
            if (BNT) { if (bOK) bReg = *(const float4*)(bPtr + (k0 + 8)); }
            else     { if (bOK) bReg = *(const float4*)(bPtr + (long long)(k0 + 8) * ldb); }
        }

#pragma unroll
        for (int kk = 0; kk < 8; kk++) {
            float ar[8], br[8];
            *(float4*)&ar[0] = *(const float4*)&As[kk][tr];
            *(float4*)&ar[4] = *(const float4*)&As[kk][tr + 4];
            *(float4*)&br[0] = *(const float4*)&Bs[kk][tc];
            *(float4*)&br[4] = *(const float4*)&Bs[kk][tc + 4];
#pragma unroll
            for (int i = 0; i < 8; i++)
#pragma unroll
                for (int j = 0; j < 8; j++)
                    acc[i][j] = fmaf(ar[i], br[j], acc[i][j]);
        }
        __syncthreads();
    }

    float gam = 1.f;
    if (FUSE) gam = __ldg(gammaPtr);

#pragma unroll
    for (int i = 0; i < 8; i++) {
        int gm = m0 + tr + i;
        if (gm < M) {
#pragma unroll
            for (int j = 0; j < 8; j += 4) {
                int gn = n0 + tc + j;
                if (gn < N) {   // N % 4 == 0 -> all-or-nothing for the float4
                    float4 o;
                    o.x = acc[i][j]; o.y = acc[i][j + 1];
                    o.z = acc[i][j + 2]; o.w = acc[i][j + 3];
                    if (bias) {
                        o.x += __ldg(bias + gn);     o.y += __ldg(bias + gn + 1);
                        o.z += __ldg(bias + gn + 2); o.w += __ldg(bias + gn + 3);
                    }
                    if (FUSE) {
                        float4 r = *(const float4*)(Rs + (long long)gm * ldc + gn);
                        o.x = fmaf(gam, o.x, r.x); o.y = fmaf(gam, o.y, r.y);
                        o.z = fmaf(gam, o.z, r.z); o.w = fmaf(gam, o.w, r.w);
                    }
                    *(float4*)(C + (long long)gm * ldc + gn) = o;
                }
            }
        }
    }
}

// ---------------------------------------------------------------------------
// conv0: y0[g][o] = b0[o] + sum_c w0[o][c] * x0[b][c][l]   (K = 8)
// block = 256 threads, 16 positions per block (same b: 16 | 1024)
// ---------------------------------------------------------------------------
__global__ __launch_bounds__(256)
void conv0_kernel(const float* __restrict__ x0, const float* __restrict__ w0,
                  const float* __restrict__ b0, float* __restrict__ y0)
{
    __shared__ float ws[C0C * CIN];     // 2048
    __shared__ float xs[CIN][16];
    const int t = threadIdx.x;
    for (int i = t; i < C0C * CIN; i += 256) ws[i] = w0[i];
    const int g0 = blockIdx.x * 16;
    const int b = g0 >> 10, l0 = g0 & 1023;
    if (t < 128) {
        int c = t >> 4, i = t & 15;
        xs[c][i] = x0[b * (CIN * LL) + c * LL + l0 + i];
    }
    __syncthreads();

    float wreg[CIN];
#pragma unroll
    for (int c = 0; c < CIN; c++) wreg[c] = ws[t * CIN + c];
    const float bb = __ldg(b0 + t);
#pragma unroll
    for (int i = 0; i < 16; i++) {
        float acc = bb;
#pragma unroll
        for (int c = 0; c < CIN; c++) acc = fmaf(wreg[c], xs[c][i], acc);
        y0[(size_t)(g0 + i) * C0C + t] = acc;
    }
}

// ---------------------------------------------------------------------------
// BN stats stage 1: deterministic per-(chunk, channel) partial sum / sumsq
// grid = (64 chunks of 1024 positions, nch/32 groups); block = 256 (8 warps)
// ---------------------------------------------------------------------------
__global__ __launch_bounds__(256)
void bnstats_partial(const float* __restrict__ y, int nch,
                     float* __restrict__ pS, float* __restrict__ pQ)
{
    const int chunk = blockIdx.x;
    const int group = blockIdx.y;
    const int t = threadIdx.x;
    const int warp = t >> 5, lane = t & 31;
    const int ch = group * 32 + lane;
    const long long base = (long long)chunk * 1024;

    float s = 0.f, q = 0.f;
    for (int r = warp; r < 1024; r += 8) {
        float v = y[(base + r) * nch + ch];
        s += v; q = fmaf(v, v, q);
    }
    __shared__ float ss[8][32], sq[8][32];
    ss[warp][lane] = s; sq[warp][lane] = q;
    __syncthreads();
    if (warp == 0) {
        float S = ss[0][lane], Q = sq[0][lane];
#pragma unroll
        for (int w = 1; w < 8; w++) { S += ss[w][lane]; Q += sq[w][lane]; }
        pS[ch * 64 + chunk] = S;
        pQ[ch * 64 + chunk] = Q;
    }
}

// BN stats stage 2: fixed-order reduction -> scale/shift per channel
__global__ void bnfinalize(const float* __restrict__ pS, const float* __restrict__ pQ,
                           const float* __restrict__ g, const float* __restrict__ be,
                           float* __restrict__ scale, float* __restrict__ shift, int nch)
{
    int ch = blockIdx.x * blockDim.x + threadIdx.x;
    if (ch >= nch) return;
    float s = 0.f, q = 0.f;
    for (int i = 0; i < 64; i++) { s += pS[ch * 64 + i]; q += pQ[ch * 64 + i]; }
    const float inv = 1.f / 65536.f;
    float mean = s * inv;
    float var = q * inv - mean * mean;
    float sc = __ldg(g + ch) * rsqrtf(var + 1e-5f);
    scale[ch] = sc;
    shift[ch] = __ldg(be + ch) - mean * sc;
}

// Apply BN + ReLU (channel = idx % nch), vectorized float4 (nch % 4 == 0)
__global__ __launch_bounds__(256)
void bnapply_relu(const float* __restrict__ y, const float* __restrict__ scale,
                  const float* __restrict__ shift, float* __restrict__ o, int nch)
{
    long long i = ((long long)blockIdx.x * blockDim.x + threadIdx.x) * 4;
    float4 v = *(const float4*)(y + i);
    int ch = (int)(i & (nch - 1));          // nch is power of two (256)
    float4 sc = *(const float4*)(scale + ch);
    float4 sh = *(const float4*)(shift + ch);
    v.x = fmaxf(fmaf(v.x, sc.x, sh.x), 0.f);
    v.y = fmaxf(fmaf(v.y, sc.y, sh.y), 0.f);
    v.z = fmaxf(fmaf(v.z, sc.z, sh.z), 0.f);
    v.w = fmaxf(fmaf(v.w, sc.w, sh.w), 0.f);
    *(float4*)(o + i) = v;
}

// ---------------------------------------------------------------------------
// Row softmax over 1024 elements, one block per row, 256 threads x float4
// ---------------------------------------------------------------------------
__global__ __launch_bounds__(256)
void softmax_kernel(float* __restrict__ E)
{
    const long long row = blockIdx.x;
    float4* rp = (float4*)(E + row * 1024);
    const int t = threadIdx.x;
    float4 v = rp[t];

    float m = fmaxf(fmaxf(v.x, v.y), fmaxf(v.z, v.w));
#pragma unroll
    for (int o = 16; o; o >>= 1) m = fmaxf(m, __shfl_xor_sync(0xffffffffu, m, o));
    __shared__ float smax[8], ssum[8];
    const int warp = t >> 5, lane = t & 31;
    if (lane == 0) smax[warp] = m;
    __syncthreads();
    float bm = smax[0];
#pragma unroll
    for (int w = 1; w < 8; w++) bm = fmaxf(bm, smax[w]);

    v.x = __expf(v.x - bm); v.y = __expf(v.y - bm);
    v.z = __expf(v.z - bm); v.w = __expf(v.w - bm);
    float s = v.x + v.y + v.z + v.w;
#pragma unroll
    for (int o = 16; o; o >>= 1) s += __shfl_xor_sync(0xffffffffu, s, o);
    if (lane == 0) ssum[warp] = s;
    __syncthreads();
    float bs = ssum[0];
#pragma unroll
    for (int w = 1; w < 8; w++) bs += ssum[w];

    const float inv = 1.f / bs;
    v.x *= inv; v.y *= inv; v.z *= inv; v.w *= inv;
    rp[t] = v;
}

// ---------------------------------------------------------------------------
// Final: out[b][cin][l] = b_out[cin] + sum_f w_out[cin][f] * relu(bn1(x1[g][f]))
// block = 256 threads = 32 positions x 8 cin, 32 positions per block
// ---------------------------------------------------------------------------
__global__ __launch_bounds__(256)
void final_kernel(const float* __restrict__ x1,
                  const float* __restrict__ scale1, const float* __restrict__ shift1,
                  const float* __restrict__ w_out, const float* __restrict__ b_out,
                  float* __restrict__ out)
{
    __shared__ float xs[32][65];     // padded to dodge 32-way conflicts
    __shared__ float wsh[8][64];
    const int t = threadIdx.x;
    const int g0 = blockIdx.x * 32;

    for (int i = t; i < 32 * 64; i += 256) {
        int pos = i >> 6, f = i & 63;
        float v = x1[(size_t)(g0 + pos) * FFC + f];
        v = fmaf(v, __ldg(scale1 + f), __ldg(shift1 + f));
        xs[pos][f] = fmaxf(v, 0.f);
    }
    for (int i = t; i < 8 * 64; i += 256) wsh[i >> 6][i & 63] = w_out[i];
    __syncthreads();

    const int pos = t & 31, cin = t >> 5;
    float acc = __ldg(b_out + cin);
#pragma unroll
    for (int f = 0; f < 64; f++) acc = fmaf(wsh[cin][f], xs[pos][f], acc);

    const int b = g0 >> 10, l0 = g0 & 1023;
    out[b * (CIN * LL) + cin * LL + l0 + pos] = acc;
}

// ---------------------------------------------------------------------------
// Host launcher (graph-capturable: kernel launches only; cudaGetSymbolAddress
// enqueues no work and is capture-safe)
// ---------------------------------------------------------------------------
extern "C" void kernel_launch(void* const* d_in, const int* in_sizes, int n_in,
                              void* d_out, int out_size)
{
    const float* z     = (const float*)d_in[0];
    const float* w_pre = (const float*)d_in[1];
    const float* b_pre = (const float*)d_in[2];
    const float* w0    = (const float*)d_in[3];
    const float* b0    = (const float*)d_in[4];
    const float* g0    = (const float*)d_in[5];
    const float* be0   = (const float*)d_in[6];
    const float* wq    = (const float*)d_in[7];
    const float* bq    = (const float*)d_in[8];
    const float* wk    = (const float*)d_in[9];
    const float* bk    = (const float*)d_in[10];
    const float* wv    = (const float*)d_in[11];
    const float* bv    = (const float*)d_in[12];
    const float* gamma = (const float*)d_in[13];
    const float* w1    = (const float*)d_in[14];
    const float* b1    = (const float*)d_in[15];
    const float* g1    = (const float*)d_in[16];
    const float* be1   = (const float*)d_in[17];
    const float* w_out = (const float*)d_in[18];
    const float* b_out = (const float*)d_in[19];
    float* out = (float*)d_out;

    float *x0, *y0, *xa, *qkv, *E, *att, *x1, *pS, *pQ, *sc0, *sh0, *sc1, *sh1;
    cudaGetSymbolAddress((void**)&x0,  g_x0);
    cudaGetSymbolAddress((void**)&y0,  g_y0);
    cudaGetSymbolAddress((void**)&xa,  g_xa);
    cudaGetSymbolAddress((void**)&qkv, g_qkv);
    cudaGetSymbolAddress((void**)&E,   g_E);
    cudaGetSymbolAddress((void**)&att, g_att);
    cudaGetSymbolAddress((void**)&x1,  g_x1);
    cudaGetSymbolAddress((void**)&pS,  g_pS);
    cudaGetSymbolAddress((void**)&pQ,  g_pQ);
    cudaGetSymbolAddress((void**)&sc0, g_scale0);
    cudaGetSymbolAddress((void**)&sh0, g_shift0);
    cudaGetSymbolAddress((void**)&sc1, g_scale1);
    cudaGetSymbolAddress((void**)&sh1, g_shift1);

    const long long sQKV = (long long)LL * 320;
    const long long sE   = (long long)LL * LL;
    const long long sC   = (long long)LL * C0C;

    // 1) pre-linear: x0 = z @ w_pre^T + b_pre   [64 x 8192], K=128
    sgemm_kernel<1, 0><<<dim3(8192 / 128, 1, 1), 256>>>(
        z, w_pre, b_pre, nullptr, nullptr, x0,
        NB, CIN * LL, ZD, ZD, ZD, CIN * LL, 0, 0, 0);

    // 2) conv0 (K=8) -> y0 [g][256]
    conv0_kernel<<<GG / 16, 256>>>(x0, w0, b0, y0);

    // 3) BN0 stats + apply + relu -> xa
    bnstats_partial<<<dim3(64, C0C / 32), 256>>>(y0, C0C, pS, pQ);
    bnfinalize<<<1, 256>>>(pS, pQ, g0, be0, sc0, sh0, C0C);
    bnapply_relu<<<(GG * C0C) / (256 * 4), 256>>>(y0, sc0, sh0, xa, C0C);

    // 4) q / k / v projections into qkv [g][320]
    sgemm_kernel<1, 0><<<dim3(1, GG / 128, 1), 256>>>(
        xa, wq, bq, nullptr, nullptr, qkv,       GG, CQKC, C0C, C0C, C0C, 320, 0, 0, 0);
    sgemm_kernel<1, 0><<<dim3(1, GG / 128, 1), 256>>>(
        xa, wk, bk, nullptr, nullptr, qkv + 32,  GG, CQKC, C0C, C0C, C0C, 320, 0, 0, 0);
    sgemm_kernel<1, 0><<<dim3(2, GG / 128, 1), 256>>>(
        xa, wv, bv, nullptr, nullptr, qkv + 64,  GG, C0C,  C0C, C0C, C0C, 320, 0, 0, 0);

    // 5) energy: E[b] = Q[b] K[b]^T   (M=N=1024, K=32), batched over 64
    sgemm_kernel<1, 0><<<dim3(8, 8, NB), 256>>>(
        qkv, qkv + 32, nullptr, nullptr, nullptr, E,
        LL, LL, CQKC, 320, 320, LL, sQKV, sQKV, sE);

    // 6) row softmax
    softmax_kernel<<<GG, 256>>>(E);

    // 7) att = gamma * (A @ V) + xa   (M=1024, N=256, K=1024), fused residual
    sgemm_kernel<0, 1><<<dim3(2, 8, NB), 256>>>(
        E, qkv + 64, nullptr, xa, gamma, att,
        LL, C0C, LL, LL, 320, C0C, sE, sQKV, sC);

    // 8) conv1: x1 = att @ w1^T + b1   [g][64], K=256
    sgemm_kernel<1, 0><<<dim3(1, GG / 128, 1), 256>>>(
        att, w1, b1, nullptr, nullptr, x1, GG, FFC, C0C, C0C, C0C, FFC, 0, 0, 0);

    // 9) BN1 stats
    bnstats_partial<<<dim3(64, FFC / 32), 256>>>(x1, FFC, pS, pQ);
    bnfinalize<<<1, 64>>>(pS, pQ, g1, be1, sc1, sh1, FFC);

    // 10) fused BN1 + relu + w_out conv -> out [b][8][1024]
    final_kernel<<<GG / 32, 256>>>(x1, sc1, sh1, w_out, b_out, out);

    (void)in_sizes; (void)n_in; (void)out_size;
}

// round 4
// speedup vs baseline: 1.4423x; 1.4423x over previous
#include <cuda_runtime.h>
#include <cuda_bf16.h>

// ---------------------------------------------------------------------------
// Problem constants
// ---------------------------------------------------------------------------
#define NB    64          // batch
#define ZD    128         // latent dim
#define CIN   8
#define LL    1024        // W*H
#define C0C   256         // attention channels
#define CQKC  32
#define FFC   64          // filters
#define GG    65536       // NB * LL (total positions)

// ---------------------------------------------------------------------------
// Device scratch (allocation-free rule: __device__ globals)
// ---------------------------------------------------------------------------
__device__ __align__(16) float g_x0 [NB * CIN * LL];          //  2 MB
__device__ __align__(16) float g_y0 [(size_t)GG * C0C];       // 64 MB
__device__ __align__(16) float g_xa [(size_t)GG * C0C];       // 64 MB
__device__ __align__(16) float g_qkv[(size_t)GG * 320];       // 80 MB [g][q32|k32|v256]
__device__ __align__(16) float g_E  [(size_t)NB * LL * LL];   // 256 MB fp32 energies
__device__ __align__(16) __nv_bfloat16 g_Eh [(size_t)GG * LL];   // 128 MB softmax hi
__device__ __align__(16) __nv_bfloat16 g_El [(size_t)GG * LL];   // 128 MB softmax lo
__device__ __align__(16) __nv_bfloat16 g_vTh[(size_t)NB * C0C * LL]; // 32 MB V^T hi
__device__ __align__(16) __nv_bfloat16 g_vTl[(size_t)NB * C0C * LL]; // 32 MB V^T lo
__device__ __align__(16) float g_att[(size_t)GG * C0C];       // 64 MB
__device__ __align__(16) float g_x1 [(size_t)GG * FFC];       // 16 MB
__device__ float g_pS[C0C * 64];
__device__ float g_pQ[C0C * 64];
__device__ __align__(16) float g_scale0[C0C], g_shift0[C0C];
__device__ __align__(16) float g_scale1[FFC], g_shift1[FFC];

// ---------------------------------------------------------------------------
// PTX helpers (sm_80-level only: cp.async, ldmatrix, mma.sync — NO sm_100a
// features; the harness's ptxas targets plain sm_100)
// ---------------------------------------------------------------------------
__device__ __forceinline__ unsigned smem_u32(const void* p) {
    unsigned a;
    asm("{ .reg .u64 t; cvta.to.shared.u64 t, %1; cvt.u32.u64 %0, t; }" : "=r"(a) : "l"(p));
    return a;
}
__device__ __forceinline__ void cpasync16(unsigned d, const void* s) {
    asm volatile("cp.async.cg.shared.global [%0], [%1], 16;" :: "r"(d), "l"(s));
}
#define CP_COMMIT() asm volatile("cp.async.commit_group;" ::: "memory")
#define CP_WAIT0()  asm volatile("cp.async.wait_group 0;" ::: "memory")
#define CP_WAIT1()  asm volatile("cp.async.wait_group 1;" ::: "memory")

__device__ __forceinline__ void ldsm_x4(unsigned& r0, unsigned& r1,
                                        unsigned& r2, unsigned& r3, unsigned addr) {
    asm volatile("ldmatrix.sync.aligned.m8n8.x4.shared.b16 {%0,%1,%2,%3}, [%4];"
                 : "=r"(r0), "=r"(r1), "=r"(r2), "=r"(r3) : "r"(addr));
}
__device__ __forceinline__ void mma_bf16(float* c, const unsigned* a, const unsigned* b) {
    asm volatile("mma.sync.aligned.m16n8k16.row.col.f32.bf16.bf16.f32 "
                 "{%0,%1,%2,%3}, {%4,%5,%6,%7}, {%8,%9}, {%0,%1,%2,%3};"
                 : "+f"(c[0]), "+f"(c[1]), "+f"(c[2]), "+f"(c[3])
                 : "r"(a[0]), "r"(a[1]), "r"(a[2]), "r"(a[3]), "r"(b[0]), "r"(b[1]));
}

// ---------------------------------------------------------------------------
// Generic tiled SGEMM (fp32 SIMT), B stored [N,K] row-major.
// 128x128x8 tile, 256 threads, 8x8 microtile, register-prefetch pipelined.
// ---------------------------------------------------------------------------
__global__ __launch_bounds__(256)
void sgemm_kernel(const float* __restrict__ A, const float* __restrict__ Bm,
                  const float* __restrict__ bias, float* __restrict__ C,
                  int M, int N, int K, int lda, int ldb, int ldc,
                  long long sA, long long sB, long long sC)
{
    __shared__ float As[8][128];
    __shared__ float Bs[8][128];

    const int bz = blockIdx.z;
    A  += (long long)bz * sA;
    Bm += (long long)bz * sB;
    C  += (long long)bz * sC;

    const int tid = threadIdx.x;
    const int m0 = blockIdx.y * 128;
    const int n0 = blockIdx.x * 128;

    const int aRow = tid >> 1;
    const int aK   = (tid & 1) << 2;
    const int tr = (tid >> 4) << 3;
    const int tc = (tid & 15) << 3;

    const bool aOK = (m0 + aRow) < M;
    const bool bOK = (n0 + aRow) < N;
    const float* aPtr = A + (long long)(m0 + aRow) * lda + aK;
    const float* bPtr = Bm + (long long)(n0 + aRow) * ldb + aK;

    float acc[8][8];
#pragma unroll
    for (int i = 0; i < 8; i++)
#pragma unroll
        for (int j = 0; j < 8; j++) acc[i][j] = 0.f;

    float4 aReg = make_float4(0.f, 0.f, 0.f, 0.f);
    float4 bReg = make_float4(0.f, 0.f, 0.f, 0.f);
    if (aOK) aReg = *(const float4*)aPtr;
    if (bOK) bReg = *(const float4*)bPtr;

    for (int k0 = 0; k0 < K; k0 += 8) {
        As[aK + 0][aRow] = aReg.x; As[aK + 1][aRow] = aReg.y;
        As[aK + 2][aRow] = aReg.z; As[aK + 3][aRow] = aReg.w;
        Bs[aK + 0][aRow] = bReg.x; Bs[aK + 1][aRow] = bReg.y;
        Bs[aK + 2][aRow] = bReg.z; Bs[aK + 3][aRow] = bReg.w;
        __syncthreads();

        if (k0 + 8 < K) {
            aReg = make_float4(0.f, 0.f, 0.f, 0.f);
            bReg = make_float4(0.f, 0.f, 0.f, 0.f);
            if (aOK) aReg = *(const float4*)(aPtr + (k0 + 8));
            if (bOK) bReg = *(const float4*)(bPtr + (k0 + 8));
        }

#pragma unroll
        for (int kk = 0; kk < 8; kk++) {
            float ar[8], br[8];
            *(float4*)&ar[0] = *(const float4*)&As[kk][tr];
            *(float4*)&ar[4] = *(const float4*)&As[kk][tr + 4];
            *(float4*)&br[0] = *(const float4*)&Bs[kk][tc];
            *(float4*)&br[4] = *(const float4*)&Bs[kk][tc + 4];
#pragma unroll
            for (int i = 0; i < 8; i++)
#pragma unroll
                for (int j = 0; j < 8; j++)
                    acc[i][j] = fmaf(ar[i], br[j], acc[i][j]);
        }
        __syncthreads();
    }

#pragma unroll
    for (int i = 0; i < 8; i++) {
        int gm = m0 + tr + i;
        if (gm < M) {
#pragma unroll
            for (int j = 0; j < 8; j += 4) {
                int gn = n0 + tc + j;
                if (gn < N) {
                    float4 o;
                    o.x = acc[i][j]; o.y = acc[i][j + 1];
                    o.z = acc[i][j + 2]; o.w = acc[i][j + 3];
                    if (bias) {
                        o.x += __ldg(bias + gn);     o.y += __ldg(bias + gn + 1);
                        o.z += __ldg(bias + gn + 2); o.w += __ldg(bias + gn + 3);
                    }
                    *(float4*)(C + (long long)gm * ldc + gn) = o;
                }
            }
        }
    }
}

// ---------------------------------------------------------------------------
// conv0: y0[g][o] = b0[o] + sum_c w0[o][c] * x0[b][c][l]   (K = 8)
// ---------------------------------------------------------------------------
__global__ __launch_bounds__(256)
void conv0_kernel(const float* __restrict__ x0, const float* __restrict__ w0,
                  const float* __restrict__ b0, float* __restrict__ y0)
{
    __shared__ float ws[C0C * CIN];
    __shared__ float xs[CIN][16];
    const int t = threadIdx.x;
    for (int i = t; i < C0C * CIN; i += 256) ws[i] = w0[i];
    const int g0 = blockIdx.x * 16;
    const int b = g0 >> 10, l0 = g0 & 1023;
    if (t < 128) {
        int c = t >> 4, i = t & 15;
        xs[c][i] = x0[b * (CIN * LL) + c * LL + l0 + i];
    }
    __syncthreads();

    float wreg[CIN];
#pragma unroll
    for (int c = 0; c < CIN; c++) wreg[c] = ws[t * CIN + c];
    const float bb = __ldg(b0 + t);
#pragma unroll
    for (int i = 0; i < 16; i++) {
        float acc = bb;
#pragma unroll
        for (int c = 0; c < CIN; c++) acc = fmaf(wreg[c], xs[c][i], acc);
        y0[(size_t)(g0 + i) * C0C + t] = acc;
    }
}

// ---------------------------------------------------------------------------
// BN stats (deterministic two-stage) + apply
// ---------------------------------------------------------------------------
__global__ __launch_bounds__(256)
void bnstats_partial(const float* __restrict__ y, int nch,
                     float* __restrict__ pS, float* __restrict__ pQ)
{
    const int chunk = blockIdx.x;
    const int group = blockIdx.y;
    const int t = threadIdx.x;
    const int warp = t >> 5, lane = t & 31;
    const int ch = group * 32 + lane;
    const long long base = (long long)chunk * 1024;

    float s = 0.f, q = 0.f;
    for (int r = warp; r < 1024; r += 8) {
        float v = y[(base + r) * nch + ch];
        s += v; q = fmaf(v, v, q);
    }
    __shared__ float ss[8][32], sq[8][32];
    ss[warp][lane] = s; sq[warp][lane] = q;
    __syncthreads();
    if (warp == 0) {
        float S = ss[0][lane], Q = sq[0][lane];
#pragma unroll
        for (int w = 1; w < 8; w++) { S += ss[w][lane]; Q += sq[w][lane]; }
        pS[ch * 64 + chunk] = S;
        pQ[ch * 64 + chunk] = Q;
    }
}

__global__ void bnfinalize(const float* __restrict__ pS, const float* __restrict__ pQ,
                           const float* __restrict__ g, const float* __restrict__ be,
                           float* __restrict__ scale, float* __restrict__ shift, int nch)
{
    int ch = blockIdx.x * blockDim.x + threadIdx.x;
    if (ch >= nch) return;
    float s = 0.f, q = 0.f;
    for (int i = 0; i < 64; i++) { s += pS[ch * 64 + i]; q += pQ[ch * 64 + i]; }
    const float inv = 1.f / 65536.f;
    float mean = s * inv;
    float var = q * inv - mean * mean;
    float sc = __ldg(g + ch) * rsqrtf(var + 1e-5f);
    scale[ch] = sc;
    shift[ch] = __ldg(be + ch) - mean * sc;
}

__global__ __launch_bounds__(256)
void bnapply_relu(const float* __restrict__ y, const float* __restrict__ scale,
                  const float* __restrict__ shift, float* __restrict__ o, int nch)
{
    long long i = ((long long)blockIdx.x * blockDim.x + threadIdx.x) * 4;
    float4 v = *(const float4*)(y + i);
    int ch = (int)(i & (nch - 1));
    float4 sc = *(const float4*)(scale + ch);
    float4 sh = *(const float4*)(shift + ch);
    v.x = fmaxf(fmaf(v.x, sc.x, sh.x), 0.f);
    v.y = fmaxf(fmaf(v.y, sc.y, sh.y), 0.f);
    v.z = fmaxf(fmaf(v.z, sc.z, sh.z), 0.f);
    v.w = fmaxf(fmaf(v.w, sc.w, sh.w), 0.f);
    *(float4*)(o + i) = v;
}

// ---------------------------------------------------------------------------
// V transpose + bf16 hi/lo split: qkv v-part [b][j][n] -> vT{h,l}[b][n][j]
// ---------------------------------------------------------------------------
__global__ __launch_bounds__(256)
void vt_kernel(const float* __restrict__ qkv,
               __nv_bfloat16* __restrict__ vTh, __nv_bfloat16* __restrict__ vTl)
{
    __shared__ float tile[32][33];
    const int b = blockIdx.z;
    const int j0 = blockIdx.x * 32;
    const int n0 = blockIdx.y * 32;
    const int tx = threadIdx.x, ty = threadIdx.y;

#pragma unroll
    for (int jj = 0; jj < 4; jj++) {
        int j = j0 + ty * 4 + jj;
        tile[ty * 4 + jj][tx] = qkv[(size_t)(b * 1024 + j) * 320 + 64 + n0 + tx];
    }
    __syncthreads();
#pragma unroll
    for (int nn = 0; nn < 4; nn++) {
        int n = n0 + ty * 4 + nn;
        float v = tile[tx][ty * 4 + nn];
        __nv_bfloat16 h = __float2bfloat16(v);
        __nv_bfloat16 l = __float2bfloat16(v - __bfloat162float(h));
        size_t o = (size_t)(b * 256 + n) * 1024 + j0 + tx;
        vTh[o] = h; vTl[o] = l;
    }
}

// ---------------------------------------------------------------------------
// Row softmax over 1024 elems; emits bf16 hi/lo split
// ---------------------------------------------------------------------------
__global__ __launch_bounds__(256)
void softmax_kernel(const float* __restrict__ E,
                    __nv_bfloat16* __restrict__ Eh, __nv_bfloat16* __restrict__ El)
{
    const long long row = blockIdx.x;
    const float4* rp = (const float4*)(E + row * 1024);
    const int t = threadIdx.x;
    float4 v = rp[t];

    float m = fmaxf(fmaxf(v.x, v.y), fmaxf(v.z, v.w));
#pragma unroll
    for (int o = 16; o; o >>= 1) m = fmaxf(m, __shfl_xor_sync(0xffffffffu, m, o));
    __shared__ float smax[8], ssum[8];
    const int warp = t >> 5, lane = t & 31;
    if (lane == 0) smax[warp] = m;
    __syncthreads();
    float bm = smax[0];
#pragma unroll
    for (int w = 1; w < 8; w++) bm = fmaxf(bm, smax[w]);

    v.x = __expf(v.x - bm); v.y = __expf(v.y - bm);
    v.z = __expf(v.z - bm); v.w = __expf(v.w - bm);
    float s = v.x + v.y + v.z + v.w;
#pragma unroll
    for (int o = 16; o; o >>= 1) s += __shfl_xor_sync(0xffffffffu, s, o);
    if (lane == 0) ssum[warp] = s;
    __syncthreads();
    float bs = ssum[0];
#pragma unroll
    for (int w = 1; w < 8; w++) bs += ssum[w];

    const float inv = 1.f / bs;
    v.x *= inv; v.y *= inv; v.z *= inv; v.w *= inv;

    __nv_bfloat16 h0 = __float2bfloat16(v.x), h1 = __float2bfloat16(v.y);
    __nv_bfloat16 h2 = __float2bfloat16(v.z), h3 = __float2bfloat16(v.w);
    __nv_bfloat16 l0 = __float2bfloat16(v.x - __bfloat162float(h0));
    __nv_bfloat16 l1 = __float2bfloat16(v.y - __bfloat162float(h1));
    __nv_bfloat16 l2 = __float2bfloat16(v.z - __bfloat162float(h2));
    __nv_bfloat16 l3 = __float2bfloat16(v.w - __bfloat162float(h3));
    size_t o = (size_t)row * 1024 + t * 4;
    *(__nv_bfloat162*)(Eh + o)     = __halves2bfloat162(h0, h1);
    *(__nv_bfloat162*)(Eh + o + 2) = __halves2bfloat162(h2, h3);
    *(__nv_bfloat162*)(El + o)     = __halves2bfloat162(l0, l1);
    *(__nv_bfloat162*)(El + o + 2) = __halves2bfloat162(l2, l3);
}

// ---------------------------------------------------------------------------
// PV mma.sync kernel: att[b][m][n] = gamma * sum_j P[b][m][j] V[b][j][n] + resid
// CTA: 128x128 output tile, K=1024 in 32 stages of Kc=32.
// Operands bf16 hi/lo split -> 3 mma passes (hh, hl, lh).
// smem: per stage 4 operands x 128 rows x 80B pitch (64B data) = 40960B, x2.
// 80B pitch makes ldmatrix 16B row-segments cover all 32 banks (conflict-free).
// ---------------------------------------------------------------------------
#define PV_OP_BYTES 10240
#define PV_STAGE_BYTES 40960
#define PV_SMEM (2 * PV_STAGE_BYTES)   // 81920

__device__ __forceinline__ void pv_load(unsigned dst, int t,
    const char* a0, const char* a1, const char* b0, const char* b1, int kByte)
{
#pragma unroll
    for (int u = 0; u < 8; u++) {
        int i = t + u * 256;
        int op = i >> 9, row = (i >> 2) & 127, c = i & 3;
        const char* s = (op == 0) ? a0 : (op == 1) ? a1 : (op == 2) ? b0 : b1;
        cpasync16(dst + op * PV_OP_BYTES + row * 80 + c * 16,
                  s + (size_t)row * 2048 + kByte + c * 16);
    }
}

__global__ __launch_bounds__(256, 1)
void pv_kernel(const __nv_bfloat16* __restrict__ Eh, const __nv_bfloat16* __restrict__ El,
               const __nv_bfloat16* __restrict__ vTh, const __nv_bfloat16* __restrict__ vTl,
               const float* __restrict__ resid, const float* __restrict__ gammaPtr,
               float* __restrict__ att)
{
    extern __shared__ char smem[];
    const unsigned sb = smem_u32(smem);
    const int t = threadIdx.x;
    const int m0 = blockIdx.x * 128, n0 = blockIdx.y * 128, b = blockIdx.z;

    const char* gAh = (const char*)Eh  + (size_t)(b * 1024 + m0) * 2048;
    const char* gAl = (const char*)El  + (size_t)(b * 1024 + m0) * 2048;
    const char* gBh = (const char*)vTh + (size_t)(b * 256 + n0) * 2048;
    const char* gBl = (const char*)vTl + (size_t)(b * 256 + n0) * 2048;

    const int w = t >> 5, lane = t & 31;
    const int wm = (w & 1) * 64, wn = (w >> 1) * 32;
    // ldmatrix lane->row/chunk mapping (x4)
    const int aRowSel = (lane & 7) + ((lane >> 3) & 1) * 8;   // A mats: {r0-7 klo, r8-15 klo, r0-7 khi, r8-15 khi}
    const int aChunk  = (lane >> 4) * 16;
    const int bRowSel = (lane & 7) + (lane >> 4) * 8;         // B mats: {n0-7 klo, n0-7 khi, n8-15 klo, n8-15 khi}
    const int bChunk  = ((lane >> 3) & 1) * 16;

    float acc[4][4][4];
#pragma unroll
    for (int mi = 0; mi < 4; mi++)
#pragma unroll
        for (int ni = 0; ni < 4; ni++)
#pragma unroll
            for (int r = 0; r < 4; r++) acc[mi][ni][r] = 0.f;

    pv_load(sb, t, gAh, gAl, gBh, gBl, 0);
    CP_COMMIT();

    for (int s = 0; s < 32; s++) {
        if (s + 1 < 32) {
            pv_load(sb + ((s + 1) & 1) * PV_STAGE_BYTES, t, gAh, gAl, gBh, gBl, (s + 1) * 64);
            CP_COMMIT();
            CP_WAIT1();
        } else {
            CP_WAIT0();
        }
        __syncthreads();

        const unsigned base = sb + (s & 1) * PV_STAGE_BYTES;
#pragma unroll
        for (int s2 = 0; s2 < 2; s2++) {
            unsigned ah[4][4], al[4][4];
#pragma unroll
            for (int mi = 0; mi < 4; mi++) {
                unsigned ar = base + (wm + mi * 16 + aRowSel) * 80 + s2 * 32 + aChunk;
                ldsm_x4(ah[mi][0], ah[mi][1], ah[mi][2], ah[mi][3], ar);
                ldsm_x4(al[mi][0], al[mi][1], al[mi][2], al[mi][3], ar + PV_OP_BYTES);
            }
            unsigned bh[4][2], bl[4][2];
#pragma unroll
            for (int ngi = 0; ngi < 2; ngi++) {
                unsigned br = base + 2 * PV_OP_BYTES + (wn + ngi * 16 + bRowSel) * 80 + s2 * 32 + bChunk;
                unsigned r0, r1, r2, r3;
                ldsm_x4(r0, r1, r2, r3, br);
                bh[2 * ngi][0] = r0; bh[2 * ngi][1] = r1;
                bh[2 * ngi + 1][0] = r2; bh[2 * ngi + 1][1] = r3;
                ldsm_x4(r0, r1, r2, r3, br + PV_OP_BYTES);
                bl[2 * ngi][0] = r0; bl[2 * ngi][1] = r1;
                bl[2 * ngi + 1][0] = r2; bl[2 * ngi + 1][1] = r3;
            }
#pragma unroll
            for (int mi = 0; mi < 4; mi++)
#pragma unroll
                for (int ni = 0; ni < 4; ni++) {
                    mma_bf16(acc[mi][ni], ah[mi], bh[ni]);
                    mma_bf16(acc[mi][ni], ah[mi], bl[ni]);
                    mma_bf16(acc[mi][ni], al[mi], bh[ni]);
                }
        }
        __syncthreads();
    }

    // epilogue: gamma * acc + resid
    const float gam = __ldg(gammaPtr);
    const int g = lane >> 2, tg = lane & 3;
#pragma unroll
    for (int mi = 0; mi < 4; mi++) {
#pragma unroll
        for (int ni = 0; ni < 4; ni++) {
            int gr = b * 1024 + m0 + wm + mi * 16 + g;
            int gc = n0 + wn + ni * 8 + 2 * tg;
            size_t i0 = (size_t)gr * 256 + gc;
            float2 r0 = *(const float2*)(resid + i0);
            float2 o0;
            o0.x = fmaf(gam, acc[mi][ni][0], r0.x);
            o0.y = fmaf(gam, acc[mi][ni][1], r0.y);
            *(float2*)(att + i0) = o0;
            size_t i1 = i0 + (size_t)8 * 256;
            float2 r1 = *(const float2*)(resid + i1);
            float2 o1;
            o1.x = fmaf(gam, acc[mi][ni][2], r1.x);
            o1.y = fmaf(gam, acc[mi][ni][3], r1.y);
            *(float2*)(att + i1) = o1;
        }
    }
}

// ---------------------------------------------------------------------------
// Final: out[b][cin][l] = b_out[cin] + sum_f w_out[cin][f] * relu(bn1(x1[g][f]))
// ---------------------------------------------------------------------------
__global__ __launch_bounds__(256)
void final_kernel(const float* __restrict__ x1,
                  const float* __restrict__ scale1, const float* __restrict__ shift1,
                  const float* __restrict__ w_out, const float* __restrict__ b_out,
                  float* __restrict__ out)
{
    __shared__ float xs[32][65];
    __shared__ float wsh[8][64];
    const int t = threadIdx.x;
    const int g0 = blockIdx.x * 32;

    for (int i = t; i < 32 * 64; i += 256) {
        int pos = i >> 6, f = i & 63;
        float v = x1[(size_t)(g0 + pos) * FFC + f];
        v = fmaf(v, __ldg(scale1 + f), __ldg(shift1 + f));
        xs[pos][f] = fmaxf(v, 0.f);
    }
    for (int i = t; i < 8 * 64; i += 256) wsh[i >> 6][i & 63] = w_out[i];
    __syncthreads();

    const int pos = t & 31, cin = t >> 5;
    float acc = __ldg(b_out + cin);
#pragma unroll
    for (int f = 0; f < 64; f++) acc = fmaf(wsh[cin][f], xs[pos][f], acc);

    const int b = g0 >> 10, l0 = g0 & 1023;
    out[b * (CIN * LL) + cin * LL + l0 + pos] = acc;
}

// ---------------------------------------------------------------------------
// Host launcher (graph-capturable: kernel launches only)
// ---------------------------------------------------------------------------
extern "C" void kernel_launch(void* const* d_in, const int* in_sizes, int n_in,
                              void* d_out, int out_size)
{
    const float* z     = (const float*)d_in[0];
    const float* w_pre = (const float*)d_in[1];
    const float* b_pre = (const float*)d_in[2];
    const float* w0    = (const float*)d_in[3];
    const float* b0    = (const float*)d_in[4];
    const float* g0    = (const float*)d_in[5];
    const float* be0   = (const float*)d_in[6];
    const float* wq    = (const float*)d_in[7];
    const float* bq    = (const float*)d_in[8];
    const float* wk    = (const float*)d_in[9];
    const float* bk    = (const float*)d_in[10];
    const float* wv    = (const float*)d_in[11];
    const float* bv    = (const float*)d_in[12];
    const float* gamma = (const float*)d_in[13];
    const float* w1    = (const float*)d_in[14];
    const float* b1    = (const float*)d_in[15];
    const float* g1    = (const float*)d_in[16];
    const float* be1   = (const float*)d_in[17];
    const float* w_out = (const float*)d_in[18];
    const float* b_out = (const float*)d_in[19];
    float* out = (float*)d_out;

    float *x0, *y0, *xa, *qkv, *E, *att, *x1, *pS, *pQ, *sc0, *sh0, *sc1, *sh1;
    __nv_bfloat16 *Eh, *El, *vTh, *vTl;
    cudaGetSymbolAddress((void**)&x0,  g_x0);
    cudaGetSymbolAddress((void**)&y0,  g_y0);
    cudaGetSymbolAddress((void**)&xa,  g_xa);
    cudaGetSymbolAddress((void**)&qkv, g_qkv);
    cudaGetSymbolAddress((void**)&E,   g_E);
    cudaGetSymbolAddress((void**)&Eh,  g_Eh);
    cudaGetSymbolAddress((void**)&El,  g_El);
    cudaGetSymbolAddress((void**)&vTh, g_vTh);
    cudaGetSymbolAddress((void**)&vTl, g_vTl);
    cudaGetSymbolAddress((void**)&att, g_att);
    cudaGetSymbolAddress((void**)&x1,  g_x1);
    cudaGetSymbolAddress((void**)&pS,  g_pS);
    cudaGetSymbolAddress((void**)&pQ,  g_pQ);
    cudaGetSymbolAddress((void**)&sc0, g_scale0);
    cudaGetSymbolAddress((void**)&sh0, g_shift0);
    cudaGetSymbolAddress((void**)&sc1, g_scale1);
    cudaGetSymbolAddress((void**)&sh1, g_shift1);

    cudaFuncSetAttribute(pv_kernel, cudaFuncAttributeMaxDynamicSharedMemorySize, PV_SMEM);

    const long long sQKV = (long long)LL * 320;
    const long long sE   = (long long)LL * LL;

    // 1) pre-linear: x0 = z @ w_pre^T + b_pre   [64 x 8192], K=128
    sgemm_kernel<<<dim3(8192 / 128, 1, 1), 256>>>(
        z, w_pre, b_pre, x0, NB, CIN * LL, ZD, ZD, ZD, CIN * LL, 0, 0, 0);

    // 2) conv0 (K=8) -> y0 [g][256]
    conv0_kernel<<<GG / 16, 256>>>(x0, w0, b0, y0);

    // 3) BN0 stats + apply + relu -> xa
    bnstats_partial<<<dim3(64, C0C / 32), 256>>>(y0, C0C, pS, pQ);
    bnfinalize<<<1, 256>>>(pS, pQ, g0, be0, sc0, sh0, C0C);
    bnapply_relu<<<(GG * C0C) / (256 * 4), 256>>>(y0, sc0, sh0, xa, C0C);

    // 4) q / k / v projections into qkv [g][320]
    sgemm_kernel<<<dim3(1, GG / 128, 1), 256>>>(
        xa, wq, bq, qkv,       GG, CQKC, C0C, C0C, C0C, 320, 0, 0, 0);
    sgemm_kernel<<<dim3(1, GG / 128, 1), 256>>>(
        xa, wk, bk, qkv + 32,  GG, CQKC, C0C, C0C, C0C, 320, 0, 0, 0);
    sgemm_kernel<<<dim3(2, GG / 128, 1), 256>>>(
        xa, wv, bv, qkv + 64,  GG, C0C,  C0C, C0C, C0C, 320, 0, 0, 0);

    // 5) V -> transposed bf16 hi/lo
    vt_kernel<<<dim3(32, 8, NB), dim3(32, 8)>>>(qkv, vTh, vTl);

    // 6) energy: E[b] = Q[b] K[b]^T   (M=N=1024, K=32), batched over 64
    sgemm_kernel<<<dim3(8, 8, NB), 256>>>(
        qkv, qkv + 32, nullptr, E, LL, LL, CQKC, 320, 320, LL, sQKV, sQKV, sE);

    // 7) row softmax -> bf16 hi/lo probabilities
    softmax_kernel<<<GG, 256>>>(E, Eh, El);

    // 8) att = gamma * (P @ V) + xa   — mma.sync bf16 split
    pv_kernel<<<dim3(8, 2, NB), 256, PV_SMEM>>>(Eh, El, vTh, vTl, xa, gamma, att);

    // 9) conv1: x1 = att @ w1^T + b1   [g][64], K=256
    sgemm_kernel<<<dim3(1, GG / 128, 1), 256>>>(
        att, w1, b1, x1, GG, FFC, C0C, C0C, C0C, FFC, 0, 0, 0);

    // 10) BN1 stats
    bnstats_partial<<<dim3(64, FFC / 32), 256>>>(x1, FFC, pS, pQ);
    bnfinalize<<<1, 64>>>(pS, pQ, g1, be1, sc1, sh1, FFC);

    // 11) fused BN1 + relu + w_out conv -> out [b][8][1024]
    final_kernel<<<GG / 32, 256>>>(x1, sc1, sh1, w_out, b_out, out);

    (void)in_sizes; (void)n_in; (void)out_size;
}

// round 5
// speedup vs baseline: 2.3166x; 1.6061x over previous
#include <cuda_runtime.h>
#include <cuda_bf16.h>

// ---------------------------------------------------------------------------
// Problem constants
// ---------------------------------------------------------------------------
#define NB    64          // batch
#define ZD    128         // latent dim
#define CIN   8
#define LL    1024        // W*H
#define C0C   256         // attention channels
#define CQKC  32
#define FFC   64          // filters
#define GG    65536       // NB * LL (total positions)

// ---------------------------------------------------------------------------
// Device scratch (allocation-free rule: __device__ globals)
// ---------------------------------------------------------------------------
__device__ __align__(16) float g_x0 [NB * CIN * LL];              //  2 MB
__device__ __align__(16) float g_y0 [(size_t)GG * C0C];           // 64 MB
__device__ __align__(16) float g_xa [(size_t)GG * C0C];           // 64 MB (PV residual)
__device__ __align__(16) __nv_bfloat16 g_xah[(size_t)GG * C0C];   // 32 MB
__device__ __align__(16) __nv_bfloat16 g_xal[(size_t)GG * C0C];   // 32 MB
__device__ __align__(16) __nv_bfloat16 g_qkh[(size_t)GG * 64];    //  8 MB [g][q32|k32] hi
__device__ __align__(16) __nv_bfloat16 g_qkl[(size_t)GG * 64];    //  8 MB lo
__device__ __align__(16) float g_v  [(size_t)GG * C0C];           // 64 MB V fp32 [g][256]
__device__ __align__(16) float g_E  [(size_t)NB * LL * LL];       // 256 MB fp32 energies
__device__ __align__(16) __nv_bfloat16 g_Eh [(size_t)GG * LL];    // 128 MB softmax hi
__device__ __align__(16) __nv_bfloat16 g_El [(size_t)GG * LL];    // 128 MB softmax lo
__device__ __align__(16) __nv_bfloat16 g_vTh[(size_t)NB * C0C * LL]; // 32 MB V^T hi
__device__ __align__(16) __nv_bfloat16 g_vTl[(size_t)NB * C0C * LL]; // 32 MB V^T lo
__device__ __align__(16) __nv_bfloat16 g_atth[(size_t)GG * C0C];  // 32 MB att hi
__device__ __align__(16) __nv_bfloat16 g_attl[(size_t)GG * C0C];  // 32 MB att lo
__device__ __align__(16) float g_x1 [(size_t)GG * FFC];           // 16 MB
// split weights
__device__ __align__(16) __nv_bfloat16 g_wqkh[64 * C0C],  g_wqkl[64 * C0C];
__device__ __align__(16) __nv_bfloat16 g_wvh [C0C * C0C], g_wvl [C0C * C0C];
__device__ __align__(16) __nv_bfloat16 g_w1h [FFC * C0C], g_w1l [FFC * C0C];
__device__ __align__(16) float g_bqk[64];
__device__ float g_pS[C0C * 64];
__device__ float g_pQ[C0C * 64];
__device__ __align__(16) float g_scale0[C0C], g_shift0[C0C];
__device__ __align__(16) float g_scale1[FFC], g_shift1[FFC];

// ---------------------------------------------------------------------------
// PTX helpers (sm_80-level only — harness ptxas targets plain sm_100)
// ---------------------------------------------------------------------------
__device__ __forceinline__ unsigned smem_u32(const void* p) {
    unsigned a;
    asm("{ .reg .u64 t; cvta.to.shared.u64 t, %1; cvt.u32.u64 %0, t; }" : "=r"(a) : "l"(p));
    return a;
}
__device__ __forceinline__ void cpasync16(unsigned d, const void* s) {
    asm volatile("cp.async.cg.shared.global [%0], [%1], 16;" :: "r"(d), "l"(s));
}
#define CP_COMMIT() asm volatile("cp.async.commit_group;" ::: "memory")
#define CP_WAIT0()  asm volatile("cp.async.wait_group 0;" ::: "memory")
#define CP_WAIT1()  asm volatile("cp.async.wait_group 1;" ::: "memory")

__device__ __forceinline__ void ldsm_x4(unsigned& r0, unsigned& r1,
                                        unsigned& r2, unsigned& r3, unsigned addr) {
    asm volatile("ldmatrix.sync.aligned.m8n8.x4.shared.b16 {%0,%1,%2,%3}, [%4];"
                 : "=r"(r0), "=r"(r1), "=r"(r2), "=r"(r3) : "r"(addr));
}
__device__ __forceinline__ void mma_bf16(float* c, const unsigned* a, const unsigned* b) {
    asm volatile("mma.sync.aligned.m16n8k16.row.col.f32.bf16.bf16.f32 "
                 "{%0,%1,%2,%3}, {%4,%5,%6,%7}, {%8,%9}, {%0,%1,%2,%3};"
                 : "+f"(c[0]), "+f"(c[1]), "+f"(c[2]), "+f"(c[3])
                 : "r"(a[0]), "r"(a[1]), "r"(a[2]), "r"(a[3]), "r"(b[0]), "r"(b[1]));
}

// ---------------------------------------------------------------------------
// Generic split-bf16 MMA GEMM:
//   C[m,n] = sum_k (Ah+Al)[m,k] * (Bh+Bl)[n,k]   (3 passes: hh + hl + lh)
// A: [M,K] row-major bf16 hi/lo, B: [N,K] row-major bf16 hi/lo.
// BM=128, BN in {64,128}. Kc=32 per stage, cp.async double buffer.
// SPLIT_OUT: write Ch/Cl bf16 hi/lo instead of fp32 C.
// smem rows at 80B pitch (64B data) -> conflict-free ldmatrix.
// ---------------------------------------------------------------------------
template<int BN>
__device__ __forceinline__ void mm_load(unsigned dst, int t,
    const char* Ah, const char* Al, const char* Bh, const char* Bl,
    int ldaB, int ldbB, int m0, int n0, int kByte)
{
    constexpr int AOP = 128 * 80, BOP = BN * 80;
    constexpr int TCA = 1024, TC = TCA + BN * 8;
#pragma unroll
    for (int u = 0; u < TC / 256; u++) {
        int i = t + u * 256;
        if (i < TCA) {
            int half = i >> 9, row = (i >> 2) & 127, c = i & 3;
            const char* s = half ? Al : Ah;
            cpasync16(dst + half * AOP + row * 80 + c * 16,
                      s + (size_t)(m0 + row) * ldaB + kByte + c * 16);
        } else {
            int j = i - TCA;
            int half = j / (BN * 4), row = (j >> 2) % BN, c = j & 3;
            const char* s = half ? Bl : Bh;
            cpasync16(dst + 2 * AOP + half * BOP + row * 80 + c * 16,
                      s + (size_t)(n0 + row) * ldbB + kByte + c * 16);
        }
    }
}

template<int BN, int SPLIT_OUT>
__global__ __launch_bounds__(256, 1)
void mma_gemm(const __nv_bfloat16* __restrict__ Ah, const __nv_bfloat16* __restrict__ Al,
              int lda, long long sA,
              const __nv_bfloat16* __restrict__ Bh, const __nv_bfloat16* __restrict__ Bl,
              int ldb, long long sB,
              const float* __restrict__ bias,
              float* __restrict__ C,
              __nv_bfloat16* __restrict__ Ch, __nv_bfloat16* __restrict__ Cl,
              int ldc, long long sC, int K)
{
    constexpr int AOP = 128 * 80, BOP = BN * 80;
    constexpr int ST = 2 * AOP + 2 * BOP;
    constexpr int NW = BN / 4;      // warp n-tile
    constexpr int NI = NW / 8;      // n8 frags per warp
    constexpr int NGI = NW / 16;    // ldsm.x4 groups per warp

    extern __shared__ char smem[];
    const unsigned sb = smem_u32(smem);
    const int t = threadIdx.x;
    const int n0 = blockIdx.x * BN, m0 = blockIdx.y * 128, z = blockIdx.z;

    const char* cAh = (const char*)(Ah + (size_t)z * sA);
    const char* cAl = (const char*)(Al + (size_t)z * sA);
    const char* cBh = (const char*)(Bh + (size_t)z * sB);
    const char* cBl = (const char*)(Bl + (size_t)z * sB);
    const int ldaB = lda * 2, ldbB = ldb * 2;

    const int w = t >> 5, lane = t & 31;
    const int wm = (w & 1) * 64, wn = (w >> 1) * NW;
    const int aRowSel = (lane & 7) + ((lane >> 3) & 1) * 8;
    const int aChunk  = (lane >> 4) * 16;
    const int bRowSel = (lane & 7) + (lane >> 4) * 8;
    const int bChunk  = ((lane >> 3) & 1) * 16;

    float acc[4][NI][4];
#pragma unroll
    for (int mi = 0; mi < 4; mi++)
#pragma unroll
        for (int ni = 0; ni < NI; ni++)
#pragma unroll
            for (int r = 0; r < 4; r++) acc[mi][ni][r] = 0.f;

    const int nst = K / 32;
    mm_load<BN>(sb, t, cAh, cAl, cBh, cBl, ldaB, ldbB, m0, n0, 0);
    CP_COMMIT();

    for (int s = 0; s < nst; s++) {
        if (s + 1 < nst) {
            mm_load<BN>(sb + ((s + 1) & 1) * ST, t, cAh, cAl, cBh, cBl,
                        ldaB, ldbB, m0, n0, (s + 1) * 64);
            CP_COMMIT();
            CP_WAIT1();
        } else {
            CP_WAIT0();
        }
        __syncthreads();

        const unsigned base = sb + (s & 1) * ST;
#pragma unroll
        for (int s2 = 0; s2 < 2; s2++) {
            unsigned ah[4][4], al[4][4];
#pragma unroll
            for (int mi = 0; mi < 4; mi++) {
                unsigned ar = base + (wm + mi * 16 + aRowSel) * 80 + s2 * 32 + aChunk;
                ldsm_x4(ah[mi][0], ah[mi][1], ah[mi][2], ah[mi][3], ar);
                ldsm_x4(al[mi][0], al[mi][1], al[mi][2], al[mi][3], ar + AOP);
            }
            unsigned bh[NI][2], bl[NI][2];
#pragma unroll
            for (int ngi = 0; ngi < NGI; ngi++) {
                unsigned br = base + 2 * AOP + (wn + ngi * 16 + bRowSel) * 80 + s2 * 32 + bChunk;
                unsigned r0, r1, r2, r3;
                ldsm_x4(r0, r1, r2, r3, br);
                bh[2 * ngi][0] = r0; bh[2 * ngi][1] = r1;
                bh[2 * ngi + 1][0] = r2; bh[2 * ngi + 1][1] = r3;
                ldsm_x4(r0, r1, r2, r3, br + BOP);
                bl[2 * ngi][0] = r0; bl[2 * ngi][1] = r1;
                bl[2 * ngi + 1][0] = r2; bl[2 * ngi + 1][1] = r3;
            }
#pragma unroll
            for (int mi = 0; mi < 4; mi++)
#pragma unroll
                for (int ni = 0; ni < NI; ni++) {
                    mma_bf16(acc[mi][ni], ah[mi], bh[ni]);
                    mma_bf16(acc[mi][ni], ah[mi], bl[ni]);
                    mma_bf16(acc[mi][ni], al[mi], bh[ni]);
                }
        }
        __syncthreads();
    }

    // epilogue
    const int g = lane >> 2, tg = lane & 3;
#pragma unroll
    for (int mi = 0; mi < 4; mi++) {
#pragma unroll
        for (int ni = 0; ni < NI; ni++) {
            int gr = m0 + wm + mi * 16 + g;
            int gc = n0 + wn + ni * 8 + 2 * tg;
            float b0 = 0.f, b1 = 0.f;
            if (bias) { b0 = __ldg(bias + gc); b1 = __ldg(bias + gc + 1); }
#pragma unroll
            for (int half = 0; half < 2; half++) {
                size_t idx = (size_t)z * sC + (size_t)(gr + half * 8) * ldc + gc;
                float v0 = acc[mi][ni][2 * half + 0] + b0;
                float v1 = acc[mi][ni][2 * half + 1] + b1;
                if (SPLIT_OUT) {
                    __nv_bfloat16 h0 = __float2bfloat16(v0), h1 = __float2bfloat16(v1);
                    __nv_bfloat16 l0 = __float2bfloat16(v0 - __bfloat162float(h0));
                    __nv_bfloat16 l1 = __float2bfloat16(v1 - __bfloat162float(h1));
                    *(__nv_bfloat162*)(Ch + idx) = __halves2bfloat162(h0, h1);
                    *(__nv_bfloat162*)(Cl + idx) = __halves2bfloat162(l0, l1);
                } else {
                    float2 o; o.x = v0; o.y = v1;
                    *(float2*)(C + idx) = o;
                }
            }
        }
    }
}

// ---------------------------------------------------------------------------
// Weight prep: split wq||wk, wv, w1 into bf16 hi/lo; merge bq||bk
// ---------------------------------------------------------------------------
__global__ void wprep_kernel(const float* __restrict__ wq, const float* __restrict__ wk,
                             const float* __restrict__ wv, const float* __restrict__ w1,
                             const float* __restrict__ bq, const float* __restrict__ bk,
                             float* __restrict__ bqk,
                             __nv_bfloat16* __restrict__ wqkh, __nv_bfloat16* __restrict__ wqkl,
                             __nv_bfloat16* __restrict__ wvh,  __nv_bfloat16* __restrict__ wvl,
                             __nv_bfloat16* __restrict__ w1h,  __nv_bfloat16* __restrict__ w1l)
{
    int i = blockIdx.x * 256 + threadIdx.x;
    if (i < 16384) {
        int n = i >> 8, k = i & 255;
        float v = (n < 32) ? wq[n * 256 + k] : wk[(n - 32) * 256 + k];
        __nv_bfloat16 h = __float2bfloat16(v);
        wqkh[i] = h; wqkl[i] = __float2bfloat16(v - __bfloat162float(h));
    } else if (i < 81920) {
        int j = i - 16384;
        float v = wv[j];
        __nv_bfloat16 h = __float2bfloat16(v);
        wvh[j] = h; wvl[j] = __float2bfloat16(v - __bfloat162float(h));
    } else if (i < 98304) {
        int j = i - 81920;
        float v = w1[j];
        __nv_bfloat16 h = __float2bfloat16(v);
        w1h[j] = h; w1l[j] = __float2bfloat16(v - __bfloat162float(h));
    }
    if (i < 64) bqk[i] = (i < 32) ? bq[i] : bk[i - 32];
}

// ---------------------------------------------------------------------------
// SIMT SGEMM (only for tiny pre-linear), B stored [N,K] row-major
// ---------------------------------------------------------------------------
__global__ __launch_bounds__(256)
void sgemm_kernel(const float* __restrict__ A, const float* __restrict__ Bm,
                  const float* __restrict__ bias, float* __restrict__ C,
                  int M, int N, int K, int lda, int ldb, int ldc)
{
    __shared__ float As[8][128];
    __shared__ float Bs[8][128];

    const int tid = threadIdx.x;
    const int m0 = blockIdx.y * 128;
    const int n0 = blockIdx.x * 128;

    const int aRow = tid >> 1;
    const int aK   = (tid & 1) << 2;
    const int tr = (tid >> 4) << 3;
    const int tc = (tid & 15) << 3;

    const bool aOK = (m0 + aRow) < M;
    const bool bOK = (n0 + aRow) < N;
    const float* aPtr = A + (long long)(m0 + aRow) * lda + aK;
    const float* bPtr = Bm + (long long)(n0 + aRow) * ldb + aK;

    float acc[8][8];
#pragma unroll
    for (int i = 0; i < 8; i++)
#pragma unroll
        for (int j = 0; j < 8; j++) acc[i][j] = 0.f;

    float4 aReg = make_float4(0.f, 0.f, 0.f, 0.f);
    float4 bReg = make_float4(0.f, 0.f, 0.f, 0.f);
    if (aOK) aReg = *(const float4*)aPtr;
    if (bOK) bReg = *(const float4*)bPtr;

    for (int k0 = 0; k0 < K; k0 += 8) {
        As[aK + 0][aRow] = aReg.x; As[aK + 1][aRow] = aReg.y;
        As[aK + 2][aRow] = aReg.z; As[aK + 3][aRow] = aReg.w;
        Bs[aK + 0][aRow] = bReg.x; Bs[aK + 1][aRow] = bReg.y;
        Bs[aK + 2][aRow] = bReg.z; Bs[aK + 3][aRow] = bReg.w;
        __syncthreads();

        if (k0 + 8 < K) {
            aReg = make_float4(0.f, 0.f, 0.f, 0.f);
            bReg = make_float4(0.f, 0.f, 0.f, 0.f);
            if (aOK) aReg = *(const float4*)(aPtr + (k0 + 8));
            if (bOK) bReg = *(const float4*)(bPtr + (k0 + 8));
        }

#pragma unroll
        for (int kk = 0; kk < 8; kk++) {
            float ar[8], br[8];
            *(float4*)&ar[0] = *(const float4*)&As[kk][tr];
            *(float4*)&ar[4] = *(const float4*)&As[kk][tr + 4];
            *(float4*)&br[0] = *(const float4*)&Bs[kk][tc];
            *(float4*)&br[4] = *(const float4*)&Bs[kk][tc + 4];
#pragma unroll
            for (int i = 0; i < 8; i++)
#pragma unroll
                for (int j = 0; j < 8; j++)
                    acc[i][j] = fmaf(ar[i], br[j], acc[i][j]);
        }
        __syncthreads();
    }

#pragma unroll
    for (int i = 0; i < 8; i++) {
        int gm = m0 + tr + i;
        if (gm < M) {
#pragma unroll
            for (int j = 0; j < 8; j += 4) {
                int gn = n0 + tc + j;
                if (gn < N) {
                    float4 o;
                    o.x = acc[i][j]; o.y = acc[i][j + 1];
                    o.z = acc[i][j + 2]; o.w = acc[i][j + 3];
                    if (bias) {
                        o.x += __ldg(bias + gn);     o.y += __ldg(bias + gn + 1);
                        o.z += __ldg(bias + gn + 2); o.w += __ldg(bias + gn + 3);
                    }
                    *(float4*)(C + (long long)gm * ldc + gn) = o;
                }
            }
        }
    }
}

// ---------------------------------------------------------------------------
// conv0: y0[g][o] = b0[o] + sum_c w0[o][c] * x0[b][c][l]   (K = 8)
// ---------------------------------------------------------------------------
__global__ __launch_bounds__(256)
void conv0_kernel(const float* __restrict__ x0, const float* __restrict__ w0,
                  const float* __restrict__ b0, float* __restrict__ y0)
{
    __shared__ float ws[C0C * CIN];
    __shared__ float xs[CIN][16];
    const int t = threadIdx.x;
    for (int i = t; i < C0C * CIN; i += 256) ws[i] = w0[i];
    const int g0 = blockIdx.x * 16;
    const int b = g0 >> 10, l0 = g0 & 1023;
    if (t < 128) {
        int c = t >> 4, i = t & 15;
        xs[c][i] = x0[b * (CIN * LL) + c * LL + l0 + i];
    }
    __syncthreads();

    float wreg[CIN];
#pragma unroll
    for (int c = 0; c < CIN; c++) wreg[c] = ws[t * CIN + c];
    const float bb = __ldg(b0 + t);
#pragma unroll
    for (int i = 0; i < 16; i++) {
        float acc = bb;
#pragma unroll
        for (int c = 0; c < CIN; c++) acc = fmaf(wreg[c], xs[c][i], acc);
        y0[(size_t)(g0 + i) * C0C + t] = acc;
    }
}

// ---------------------------------------------------------------------------
// BN stats (deterministic two-stage) + apply (+ bf16 hi/lo emit)
// ---------------------------------------------------------------------------
__global__ __launch_bounds__(256)
void bnstats_partial(const float* __restrict__ y, int nch,
                     float* __restrict__ pS, float* __restrict__ pQ)
{
    const int chunk = blockIdx.x;
    const int group = blockIdx.y;
    const int t = threadIdx.x;
    const int warp = t >> 5, lane = t & 31;
    const int ch = group * 32 + lane;
    const long long base = (long long)chunk * 1024;

    float s = 0.f, q = 0.f;
    for (int r = warp; r < 1024; r += 8) {
        float v = y[(base + r) * nch + ch];
        s += v; q = fmaf(v, v, q);
    }
    __shared__ float ss[8][32], sq[8][32];
    ss[warp][lane] = s; sq[warp][lane] = q;
    __syncthreads();
    if (warp == 0) {
        float S = ss[0][lane], Q = sq[0][lane];
#pragma unroll
        for (int w = 1; w < 8; w++) { S += ss[w][lane]; Q += sq[w][lane]; }
        pS[ch * 64 + chunk] = S;
        pQ[ch * 64 + chunk] = Q;
    }
}

__global__ void bnfinalize(const float* __restrict__ pS, const float* __restrict__ pQ,
                           const float* __restrict__ g, const float* __restrict__ be,
                           float* __restrict__ scale, float* __restrict__ shift, int nch)
{
    int ch = blockIdx.x * blockDim.x + threadIdx.x;
    if (ch >= nch) return;
    float s = 0.f, q = 0.f;
    for (int i = 0; i < 64; i++) { s += pS[ch * 64 + i]; q += pQ[ch * 64 + i]; }
    const float inv = 1.f / 65536.f;
    float mean = s * inv;
    float var = q * inv - mean * mean;
    float sc = __ldg(g + ch) * rsqrtf(var + 1e-5f);
    scale[ch] = sc;
    shift[ch] = __ldg(be + ch) - mean * sc;
}

// BN apply + ReLU -> fp32 xa + bf16 hi/lo
__global__ __launch_bounds__(256)
void bnapply_relu(const float* __restrict__ y, const float* __restrict__ scale,
                  const float* __restrict__ shift, float* __restrict__ o,
                  __nv_bfloat16* __restrict__ oh, __nv_bfloat16* __restrict__ ol, int nch)
{
    long long i = ((long long)blockIdx.x * blockDim.x + threadIdx.x) * 4;
    float4 v = *(const float4*)(y + i);
    int ch = (int)(i & (nch - 1));
    float4 sc = *(const float4*)(scale + ch);
    float4 sh = *(const float4*)(shift + ch);
    v.x = fmaxf(fmaf(v.x, sc.x, sh.x), 0.f);
    v.y = fmaxf(fmaf(v.y, sc.y, sh.y), 0.f);
    v.z = fmaxf(fmaf(v.z, sc.z, sh.z), 0.f);
    v.w = fmaxf(fmaf(v.w, sc.w, sh.w), 0.f);
    *(float4*)(o + i) = v;
    __nv_bfloat16 h0 = __float2bfloat16(v.x), h1 = __float2bfloat16(v.y);
    __nv_bfloat16 h2 = __float2bfloat16(v.z), h3 = __float2bfloat16(v.w);
    *(__nv_bfloat162*)(oh + i)     = __halves2bfloat162(h0, h1);
    *(__nv_bfloat162*)(oh + i + 2) = __halves2bfloat162(h2, h3);
    *(__nv_bfloat162*)(ol + i)     = __halves2bfloat162(
        __float2bfloat16(v.x - __bfloat162float(h0)),
        __float2bfloat16(v.y - __bfloat162float(h1)));
    *(__nv_bfloat162*)(ol + i + 2) = __halves2bfloat162(
        __float2bfloat16(v.z - __bfloat162float(h2)),
        __float2bfloat16(v.w - __bfloat162float(h3)));
}

// ---------------------------------------------------------------------------
// V transpose + bf16 hi/lo split: v [b][j][n] -> vT{h,l}[b][n][j]
// ---------------------------------------------------------------------------
__global__ __launch_bounds__(256)
void vt_kernel(const float* __restrict__ v,
               __nv_bfloat16* __restrict__ vTh, __nv_bfloat16* __restrict__ vTl)
{
    __shared__ float tile[32][33];
    const int b = blockIdx.z;
    const int j0 = blockIdx.x * 32;
    const int n0 = blockIdx.y * 32;
    const int tx = threadIdx.x, ty = threadIdx.y;

#pragma unroll
    for (int jj = 0; jj < 4; jj++) {
        int j = j0 + ty * 4 + jj;
        tile[ty * 4 + jj][tx] = v[(size_t)(b * 1024 + j) * 256 + n0 + tx];
    }
    __syncthreads();
#pragma unroll
    for (int nn = 0; nn < 4; nn++) {
        int n = n0 + ty * 4 + nn;
        float vv = tile[tx][ty * 4 + nn];
        __nv_bfloat16 h = __float2bfloat16(vv);
        __nv_bfloat16 l = __float2bfloat16(vv - __bfloat162float(h));
        size_t o = (size_t)(b * 256 + n) * 1024 + j0 + tx;
        vTh[o] = h; vTl[o] = l;
    }
}

// ---------------------------------------------------------------------------
// Row softmax over 1024 elems; emits bf16 hi/lo split
// ---------------------------------------------------------------------------
__global__ __launch_bounds__(256)
void softmax_kernel(const float* __restrict__ E,
                    __nv_bfloat16* __restrict__ Eh, __nv_bfloat16* __restrict__ El)
{
    const long long row = blockIdx.x;
    const float4* rp = (const float4*)(E + row * 1024);
    const int t = threadIdx.x;
    float4 v = rp[t];

    float m = fmaxf(fmaxf(v.x, v.y), fmaxf(v.z, v.w));
#pragma unroll
    for (int o = 16; o; o >>= 1) m = fmaxf(m, __shfl_xor_sync(0xffffffffu, m, o));
    __shared__ float smax[8], ssum[8];
    const int warp = t >> 5, lane = t & 31;
    if (lane == 0) smax[warp] = m;
    __syncthreads();
    float bm = smax[0];
#pragma unroll
    for (int w = 1; w < 8; w++) bm = fmaxf(bm, smax[w]);

    v.x = __expf(v.x - bm); v.y = __expf(v.y - bm);
    v.z = __expf(v.z - bm); v.w = __expf(v.w - bm);
    float s = v.x + v.y + v.z + v.w;
#pragma unroll
    for (int o = 16; o; o >>= 1) s += __shfl_xor_sync(0xffffffffu, s, o);
    if (lane == 0) ssum[warp] = s;
    __syncthreads();
    float bs = ssum[0];
#pragma unroll
    for (int w = 1; w < 8; w++) bs += ssum[w];

    const float inv = 1.f / bs;
    v.x *= inv; v.y *= inv; v.z *= inv; v.w *= inv;

    __nv_bfloat16 h0 = __float2bfloat16(v.x), h1 = __float2bfloat16(v.y);
    __nv_bfloat16 h2 = __float2bfloat16(v.z), h3 = __float2bfloat16(v.w);
    __nv_bfloat16 l0 = __float2bfloat16(v.x - __bfloat162float(h0));
    __nv_bfloat16 l1 = __float2bfloat16(v.y - __bfloat162float(h1));
    __nv_bfloat16 l2 = __float2bfloat16(v.z - __bfloat162float(h2));
    __nv_bfloat16 l3 = __float2bfloat16(v.w - __bfloat162float(h3));
    size_t o = (size_t)row * 1024 + t * 4;
    *(__nv_bfloat162*)(Eh + o)     = __halves2bfloat162(h0, h1);
    *(__nv_bfloat162*)(Eh + o + 2) = __halves2bfloat162(h2, h3);
    *(__nv_bfloat162*)(El + o)     = __halves2bfloat162(l0, l1);
    *(__nv_bfloat162*)(El + o + 2) = __halves2bfloat162(l2, l3);
}

// ---------------------------------------------------------------------------
// PV mma.sync kernel: att = gamma * (P @ V) + resid, emits att as bf16 hi/lo
// ---------------------------------------------------------------------------
#define PV_OP_BYTES 10240
#define PV_STAGE_BYTES 40960
#define PV_SMEM (2 * PV_STAGE_BYTES)   // 81920

__device__ __forceinline__ void pv_load(unsigned dst, int t,
    const char* a0, const char* a1, const char* b0, const char* b1, int kByte)
{
#pragma unroll
    for (int u = 0; u < 8; u++) {
        int i = t + u * 256;
        int op = i >> 9, row = (i >> 2) & 127, c = i & 3;
        const char* s = (op == 0) ? a0 : (op == 1) ? a1 : (op == 2) ? b0 : b1;
        cpasync16(dst + op * PV_OP_BYTES + row * 80 + c * 16,
                  s + (size_t)row * 2048 + kByte + c * 16);
    }
}

__global__ __launch_bounds__(256, 1)
void pv_kernel(const __nv_bfloat16* __restrict__ Eh, const __nv_bfloat16* __restrict__ El,
               const __nv_bfloat16* __restrict__ vTh, const __nv_bfloat16* __restrict__ vTl,
               const float* __restrict__ resid, const float* __restrict__ gammaPtr,
               __nv_bfloat16* __restrict__ atth, __nv_bfloat16* __restrict__ attl)
{
    extern __shared__ char smem[];
    const unsigned sb = smem_u32(smem);
    const int t = threadIdx.x;
    const int m0 = blockIdx.x * 128, n0 = blockIdx.y * 128, b = blockIdx.z;

    const char* gAh = (const char*)Eh  + (size_t)(b * 1024 + m0) * 2048;
    const char* gAl = (const char*)El  + (size_t)(b * 1024 + m0) * 2048;
    const char* gBh = (const char*)vTh + (size_t)(b * 256 + n0) * 2048;
    const char* gBl = (const char*)vTl + (size_t)(b * 256 + n0) * 2048;

    const int w = t >> 5, lane = t & 31;
    const int wm = (w & 1) * 64, wn = (w >> 1) * 32;
    const int aRowSel = (lane & 7) + ((lane >> 3) & 1) * 8;
    const int aChunk  = (lane >> 4) * 16;
    const int bRowSel = (lane & 7) + (lane >> 4) * 8;
    const int bChunk  = ((lane >> 3) & 1) * 16;

    float acc[4][4][4];
#pragma unroll
    for (int mi = 0; mi < 4; mi++)
#pragma unroll
        for (int ni = 0; ni < 4; ni++)
#pragma unroll
            for (int r = 0; r < 4; r++) acc[mi][ni][r] = 0.f;

    pv_load(sb, t, gAh, gAl, gBh, gBl, 0);
    CP_COMMIT();

    for (int s = 0; s < 32; s++) {
        if (s + 1 < 32) {
            pv_load(sb + ((s + 1) & 1) * PV_STAGE_BYTES, t, gAh, gAl, gBh, gBl, (s + 1) * 64);
            CP_COMMIT();
            CP_WAIT1();
        } else {
            CP_WAIT0();
        }
        __syncthreads();

        const unsigned base = sb + (s & 1) * PV_STAGE_BYTES;
#pragma unroll
        for (int s2 = 0; s2 < 2; s2++) {
            unsigned ah[4][4], al[4][4];
#pragma unroll
            for (int mi = 0; mi < 4; mi++) {
                unsigned ar = base + (wm + mi * 16 + aRowSel) * 80 + s2 * 32 + aChunk;
                ldsm_x4(ah[mi][0], ah[mi][1], ah[mi][2], ah[mi][3], ar);
                ldsm_x4(al[mi][0], al[mi][1], al[mi][2], al[mi][3], ar + PV_OP_BYTES);
            }
            unsigned bh[4][2], bl[4][2];
#pragma unroll
            for (int ngi = 0; ngi < 2; ngi++) {
                unsigned br = base + 2 * PV_OP_BYTES + (wn + ngi * 16 + bRowSel) * 80 + s2 * 32 + bChunk;
                unsigned r0, r1, r2, r3;
                ldsm_x4(r0, r1, r2, r3, br);
                bh[2 * ngi][0] = r0; bh[2 * ngi][1] = r1;
                bh[2 * ngi + 1][0] = r2; bh[2 * ngi + 1][1] = r3;
                ldsm_x4(r0, r1, r2, r3, br + PV_OP_BYTES);
                bl[2 * ngi][0] = r0; bl[2 * ngi][1] = r1;
                bl[2 * ngi + 1][0] = r2; bl[2 * ngi + 1][1] = r3;
            }
#pragma unroll
            for (int mi = 0; mi < 4; mi++)
#pragma unroll
                for (int ni = 0; ni < 4; ni++) {
                    mma_bf16(acc[mi][ni], ah[mi], bh[ni]);
                    mma_bf16(acc[mi][ni], ah[mi], bl[ni]);
                    mma_bf16(acc[mi][ni], al[mi], bh[ni]);
                }
        }
        __syncthreads();
    }

    // epilogue: att = gamma * acc + resid -> bf16 hi/lo
    const float gam = __ldg(gammaPtr);
    const int g = lane >> 2, tg = lane & 3;
#pragma unroll
    for (int mi = 0; mi < 4; mi++) {
#pragma unroll
        for (int ni = 0; ni < 4; ni++) {
            int gr = b * 1024 + m0 + wm + mi * 16 + g;
            int gc = n0 + wn + ni * 8 + 2 * tg;
#pragma unroll
            for (int half = 0; half < 2; half++) {
                size_t idx = (size_t)(gr + half * 8) * 256 + gc;
                float2 r = *(const float2*)(resid + idx);
                float v0 = fmaf(gam, acc[mi][ni][2 * half + 0], r.x);
                float v1 = fmaf(gam, acc[mi][ni][2 * half + 1], r.y);
                __nv_bfloat16 h0 = __float2bfloat16(v0), h1 = __float2bfloat16(v1);
                __nv_bfloat16 l0 = __float2bfloat16(v0 - __bfloat162float(h0));
                __nv_bfloat16 l1 = __float2bfloat16(v1 - __bfloat162float(h1));
                *(__nv_bfloat162*)(atth + idx) = __halves2bfloat162(h0, h1);
                *(__nv_bfloat162*)(attl + idx) = __halves2bfloat162(l0, l1);
            }
        }
    }
}

// ---------------------------------------------------------------------------
// Final: out[b][cin][l] = b_out[cin] + sum_f w_out[cin][f] * relu(bn1(x1[g][f]))
// ---------------------------------------------------------------------------
__global__ __launch_bounds__(256)
void final_kernel(const float* __restrict__ x1,
                  const float* __restrict__ scale1, const float* __restrict__ shift1,
                  const float* __restrict__ w_out, const float* __restrict__ b_out,
                  float* __restrict__ out)
{
    __shared__ float xs[32][65];
    __shared__ float wsh[8][64];
    const int t = threadIdx.x;
    const int g0 = blockIdx.x * 32;

    for (int i = t; i < 32 * 64; i += 256) {
        int pos = i >> 6, f = i & 63;
        float v = x1[(size_t)(g0 + pos) * FFC + f];
        v = fmaf(v, __ldg(scale1 + f), __ldg(shift1 + f));
        xs[pos][f] = fmaxf(v, 0.f);
    }
    for (int i = t; i < 8 * 64; i += 256) wsh[i >> 6][i & 63] = w_out[i];
    __syncthreads();

    const int pos = t & 31, cin = t >> 5;
    float acc = __ldg(b_out + cin);
#pragma unroll
    for (int f = 0; f < 64; f++) acc = fmaf(wsh[cin][f], xs[pos][f], acc);

    const int b = g0 >> 10, l0 = g0 & 1023;
    out[b * (CIN * LL) + cin * LL + l0 + pos] = acc;
}

// ---------------------------------------------------------------------------
// Host launcher (graph-capturable: kernel launches only)
// ---------------------------------------------------------------------------
extern "C" void kernel_launch(void* const* d_in, const int* in_sizes, int n_in,
                              void* d_out, int out_size)
{
    const float* z     = (const float*)d_in[0];
    const float* w_pre = (const float*)d_in[1];
    const float* b_pre = (const float*)d_in[2];
    const float* w0    = (const float*)d_in[3];
    const float* b0    = (const float*)d_in[4];
    const float* g0    = (const float*)d_in[5];
    const float* be0   = (const float*)d_in[6];
    const float* wq    = (const float*)d_in[7];
    const float* bq    = (const float*)d_in[8];
    const float* wk    = (const float*)d_in[9];
    const float* bk    = (const float*)d_in[10];
    const float* wv    = (const float*)d_in[11];
    const float* bv    = (const float*)d_in[12];
    const float* gamma = (const float*)d_in[13];
    const float* w1    = (const float*)d_in[14];
    const float* b1    = (const float*)d_in[15];
    const float* g1    = (const float*)d_in[16];
    const float* be1   = (const float*)d_in[17];
    const float* w_out = (const float*)d_in[18];
    const float* b_out = (const float*)d_in[19];
    float* out = (float*)d_out;

    float *x0, *y0, *xa, *v, *E, *x1, *pS, *pQ, *sc0, *sh0, *sc1, *sh1, *bqk;
    __nv_bfloat16 *xah, *xal, *qkh, *qkl, *Eh, *El, *vTh, *vTl, *atth, *attl;
    __nv_bfloat16 *wqkh, *wqkl, *wvh, *wvl, *w1h, *w1l;
    cudaGetSymbolAddress((void**)&x0,   g_x0);
    cudaGetSymbolAddress((void**)&y0,   g_y0);
    cudaGetSymbolAddress((void**)&xa,   g_xa);
    cudaGetSymbolAddress((void**)&xah,  g_xah);
    cudaGetSymbolAddress((void**)&xal,  g_xal);
    cudaGetSymbolAddress((void**)&qkh,  g_qkh);
    cudaGetSymbolAddress((void**)&qkl,  g_qkl);
    cudaGetSymbolAddress((void**)&v,    g_v);
    cudaGetSymbolAddress((void**)&E,    g_E);
    cudaGetSymbolAddress((void**)&Eh,   g_Eh);
    cudaGetSymbolAddress((void**)&El,   g_El);
    cudaGetSymbolAddress((void**)&vTh,  g_vTh);
    cudaGetSymbolAddress((void**)&vTl,  g_vTl);
    cudaGetSymbolAddress((void**)&atth, g_atth);
    cudaGetSymbolAddress((void**)&attl, g_attl);
    cudaGetSymbolAddress((void**)&x1,   g_x1);
    cudaGetSymbolAddress((void**)&pS,   g_pS);
    cudaGetSymbolAddress((void**)&pQ,   g_pQ);
    cudaGetSymbolAddress((void**)&sc0,  g_scale0);
    cudaGetSymbolAddress((void**)&sh0,  g_shift0);
    cudaGetSymbolAddress((void**)&sc1,  g_scale1);
    cudaGetSymbolAddress((void**)&sh1,  g_shift1);
    cudaGetSymbolAddress((void**)&wqkh, g_wqkh);
    cudaGetSymbolAddress((void**)&wqkl, g_wqkl);
    cudaGetSymbolAddress((void**)&wvh,  g_wvh);
    cudaGetSymbolAddress((void**)&wvl,  g_wvl);
    cudaGetSymbolAddress((void**)&w1h,  g_w1h);
    cudaGetSymbolAddress((void**)&w1l,  g_w1l);
    cudaGetSymbolAddress((void**)&bqk,  g_bqk);

    const int ST64  = 2 * (2 * 128 * 80 + 2 * 64 * 80);    // 61440
    const int ST128 = 2 * (2 * 128 * 80 + 2 * 128 * 80);   // 81920
    cudaFuncSetAttribute(pv_kernel, cudaFuncAttributeMaxDynamicSharedMemorySize, PV_SMEM);
    cudaFuncSetAttribute(mma_gemm<64, 0>,  cudaFuncAttributeMaxDynamicSharedMemorySize, ST64);
    cudaFuncSetAttribute(mma_gemm<64, 1>,  cudaFuncAttributeMaxDynamicSharedMemorySize, ST64);
    cudaFuncSetAttribute(mma_gemm<128, 0>, cudaFuncAttributeMaxDynamicSharedMemorySize, ST128);

    // 1) pre-linear: x0 = z @ w_pre^T + b_pre   [64 x 8192], K=128
    sgemm_kernel<<<dim3(8192 / 128, 1, 1), 256>>>(
        z, w_pre, b_pre, x0, NB, CIN * LL, ZD, ZD, ZD, CIN * LL);

    // 2) conv0 (K=8) -> y0 [g][256]; weight prep in parallel
    conv0_kernel<<<GG / 16, 256>>>(x0, w0, b0, y0);
    wprep_kernel<<<384, 256>>>(wq, wk, wv, w1, bq, bk, bqk,
                               wqkh, wqkl, wvh, wvl, w1h, w1l);

    // 3) BN0 stats + apply + relu -> xa fp32 + bf16 hi/lo
    bnstats_partial<<<dim3(64, C0C / 32), 256>>>(y0, C0C, pS, pQ);
    bnfinalize<<<1, 256>>>(pS, pQ, g0, be0, sc0, sh0, C0C);
    bnapply_relu<<<(GG * C0C) / (256 * 4), 256>>>(y0, sc0, sh0, xa, xah, xal, C0C);

    // 4) Q+K projection (split out, feeds energy): [g][64], K=256
    mma_gemm<64, 1><<<dim3(1, GG / 128, 1), 256, ST64>>>(
        xah, xal, C0C, 0, wqkh, wqkl, C0C, 0, bqk,
        nullptr, qkh, qkl, 64, 0, C0C);

    // 5) V projection: [g][256] fp32, K=256
    mma_gemm<128, 0><<<dim3(2, GG / 128, 1), 256, ST128>>>(
        xah, xal, C0C, 0, wvh, wvl, C0C, 0, bv,
        v, nullptr, nullptr, C0C, 0, C0C);

    // 6) V -> transposed bf16 hi/lo
    vt_kernel<<<dim3(32, 8, NB), dim3(32, 8)>>>(v, vTh, vTl);

    // 7) energy: E[b] = Q[b] K[b]^T  (M=N=1024, K=32), batched over 64
    mma_gemm<128, 0><<<dim3(8, 8, NB), 256, ST128>>>(
        qkh, qkl, 64, (long long)LL * 64,
        qkh + 32, qkl + 32, 64, (long long)LL * 64,
        nullptr, E, nullptr, nullptr, LL, (long long)LL * LL, CQKC);

    // 8) row softmax -> bf16 hi/lo probabilities
    softmax_kernel<<<GG, 256>>>(E, Eh, El);

    // 9) att = gamma * (P @ V) + xa  -> bf16 hi/lo (mma.sync split)
    pv_kernel<<<dim3(8, 2, NB), 256, PV_SMEM>>>(Eh, El, vTh, vTl, xa, gamma, atth, attl);

    // 10) conv1: x1 = att @ w1^T + b1  [g][64], K=256
    mma_gemm<64, 0><<<dim3(1, GG / 128, 1), 256, ST64>>>(
        atth, attl, C0C, 0, w1h, w1l, C0C, 0, b1,
        x1, nullptr, nullptr, FFC, 0, C0C);

    // 11) BN1 stats
    bnstats_partial<<<dim3(64, FFC / 32), 256>>>(x1, FFC, pS, pQ);
    bnfinalize<<<1, 64>>>(pS, pQ, g1, be1, sc1, sh1, FFC);

    // 12) fused BN1 + relu + w_out conv -> out [b][8][1024]
    final_kernel<<<GG / 32, 256>>>(x1, sc1, sh1, w_out, b_out, out);

    (void)in_sizes; (void)n_in; (void)out_size;
}